// round 7
// baseline (speedup 1.0000x reference)
#include <cuda_runtime.h>
#include <math.h>

// ProCoUNLoss — per-element f32 ops mirror the reference bit-for-bit; the two
// reductions are done (near-)exactly so the only residual vs the reference is
// the reference's own summation-order noise:
//   nrm_c  = f32(sqrt( exact-sum_d fl32(Ave_cd^2) )), clipped at 1e-12
//   proto  = fl(kappa_c * fl(Ave_cd / nrm_c))                     (f32)
//   x_nc   = f32(sqrt_f64( exact-sum_d fl32(fl32(proto+f)^2) ))   (grp8+Kahan)
//   lnu    = Debye log ive_63(x) + Miller-recurrence contamination (start M=126)
//   out    = fl(fl(fl(lnu + x) - fl(63*logf32(x))) - logc_c)

namespace {
constexpr int NB   = 256;
constexpr int DD   = 128;
constexpr int CC   = 1000;
constexpr int CPAD = 1024;
constexpr int TN   = 32;   // n tile
constexpr int TC   = 32;   // c tile
}

__device__ float g_proto[CPAD * DD];  // fl(kappa * Ave_norm), zero padded

// p(t) = u1(t)/63 + u2(t)/63^2 + u3(t)/63^3  (Debye u-polynomials)
__device__ __forceinline__ float pser_f(float t) {
    float t2 = t * t;
    float a = t * (3.0f - 5.0f * t2) * (1.0f / 1512.0f);
    float b = t2 * (81.0f + t2 * (-462.0f + 385.0f * t2)) * 2.1870954e-7f;
    float c = t2 * t * (30375.0f + t2 * (-369603.0f + t2 * (765765.0f - 425425.0f * t2)))
              * 9.643249e-12f;
    return a + b + c;
}

// Contamination of the reference's Miller recurrence (start M=126):
// log1p(-rho63) - log1p(rho0), rho63 = I127*K63/(K127*I63), rho0 = I127*K0/(K127*I0).
__device__ __forceinline__ float miller_corr(float x) {
    float w127  = sqrtf(fmaf(x, x, 16129.0f));
    float w63   = sqrtf(fmaf(x, x, 3969.0f));
    float dw127 = 16129.0f / (w127 + x);
    float dw63  = 3969.0f  / (w63  + x);
    float L127  = log1pf((127.0f + dw127) / x);
    float L63   = log1pf((63.0f  + dw63)  / x);
    float g63 = 2.0f * (12160.0f / (w127 + w63)) - 254.0f * L127 + 126.0f * L63;
    float g0  = 2.0f * dw127 - 254.0f * L127;
    float r63 = expf(g63);   // underflows to 0 for small x: correct
    float r0  = expf(g0);
    return -(r63 + r0) - 0.5f * (r63 * r63 - r0 * r0);
}

// One warp per class: nrm = f32(sqrt(exact f64 sum of fl32 squares)); then
// proto = fl(kappa * fl(Ave/nrm)) — per-element f32 identical to reference.
__global__ void setup_kernel(const float* __restrict__ Ave,
                             const float* __restrict__ kappa) {
    __shared__ float rows[8][DD];
    const int w    = threadIdx.x >> 5;
    const int lane = threadIdx.x & 31;
    const int c    = blockIdx.x * 8 + w;
    if (c >= CPAD) return;

    if (c < CC) {
        #pragma unroll
        for (int j = 0; j < 4; ++j)
            rows[w][lane + 32 * j] = Ave[c * DD + lane + 32 * j];
        __syncwarp();

        float nrm = 0.0f;
        if (lane == 0) {
            double s = 0.0;
            #pragma unroll 8
            for (int d = 0; d < DD; ++d) {
                float v = rows[w][d];
                s += (double)__fmul_rn(v, v);   // exact sum of fl32 squares
            }
            nrm = fmaxf((float)sqrt(s), 1e-12f);
        }
        nrm = __shfl_sync(0xffffffffu, nrm, 0);

        const float kap = kappa[c];
        #pragma unroll
        for (int j = 0; j < 4; ++j) {
            int d = lane + 32 * j;
            g_proto[c * DD + d] = __fmul_rn(kap, __fdiv_rn(rows[w][d], nrm));
        }
    } else {
        #pragma unroll
        for (int j = 0; j < 4; ++j)
            g_proto[c * DD + lane + 32 * j] = 0.0f;
    }
}

// 32n x 32c tile, 256 threads, 4 outputs per thread (n-strided by 8).
// S = sum of fl32 squares via groups-of-8 (f32) + Kahan across 16 groups.
__global__ __launch_bounds__(256) void proco_kernel(const float* __restrict__ feat,
                                                    const float* __restrict__ logc,
                                                    float* __restrict__ out) {
    __shared__ float fs[TN][DD + 4];
    __shared__ float ps[TC][DD + 4];

    const int c0  = blockIdx.x * TC;
    const int n0  = blockIdx.y * TN;
    const int tid = threadIdx.x;

    for (int i = tid; i < TN * DD / 4; i += 256) {
        int r = i >> 5, q = i & 31;
        float4 fv = reinterpret_cast<const float4*>(feat)[(n0 + r) * (DD / 4) + q];
        *reinterpret_cast<float4*>(&fs[r][4 * q]) = fv;
        float4 pv = reinterpret_cast<const float4*>(g_proto)[(c0 + r) * (DD / 4) + q];
        *reinterpret_cast<float4*>(&ps[r][4 * q]) = pv;
    }
    __syncthreads();

    const int cl = tid & 31;   // class lane (coalesced stores)
    const int ng = tid >> 5;   // n group; thread owns n = ng, ng+8, ng+16, ng+24

    float s[4] = {0.f, 0.f, 0.f, 0.f};
    float kc[4] = {0.f, 0.f, 0.f, 0.f};   // Kahan compensation

    #pragma unroll
    for (int grp = 0; grp < 16; ++grp) {          // 16 groups of 8 elements
        const int d0 = grp * 8;
        float4 pa = *reinterpret_cast<const float4*>(&ps[cl][d0]);
        float4 pb = *reinterpret_cast<const float4*>(&ps[cl][d0 + 4]);
        #pragma unroll
        for (int j = 0; j < 4; ++j) {
            const float* fr = &fs[ng + 8 * j][d0];
            // group sum of fl32 squares of fl32(p+f), ascending d
            float t, g;
            t = __fadd_rn(pa.x, fr[0]); g = __fmul_rn(t, t);
            t = __fadd_rn(pa.y, fr[1]); g = __fadd_rn(g, __fmul_rn(t, t));
            t = __fadd_rn(pa.z, fr[2]); g = __fadd_rn(g, __fmul_rn(t, t));
            t = __fadd_rn(pa.w, fr[3]); g = __fadd_rn(g, __fmul_rn(t, t));
            t = __fadd_rn(pb.x, fr[4]); g = __fadd_rn(g, __fmul_rn(t, t));
            t = __fadd_rn(pb.y, fr[5]); g = __fadd_rn(g, __fmul_rn(t, t));
            t = __fadd_rn(pb.z, fr[6]); g = __fadd_rn(g, __fmul_rn(t, t));
            t = __fadd_rn(pb.w, fr[7]); g = __fadd_rn(g, __fmul_rn(t, t));
            // Kahan accumulate g into (s, kc)
            float y  = __fsub_rn(g, kc[j]);
            float sn = __fadd_rn(s[j], y);
            kc[j] = __fsub_rn(__fsub_rn(sn, s[j]), y);
            s[j] = sn;
        }
    }

    const int c = c0 + cl;
    if (c >= CC) return;
    const float lc = logc[c];

    #pragma unroll
    for (int j = 0; j < 4; ++j) {
        const int n = n0 + ng + 8 * j;
        // exact S = s + kc (both f32, summed in f64); x = fl32(true sqrt)
        const double Sd = (double)s[j] + (double)kc[j];
        const float  x  = (float)sqrt(Sd);

        // lnu = log ive_63(x) (+ Miller contamination), f32 with f64 logs
        const double xd  = (double)x;
        const double Ld  = log(xd);
        const float  L   = (float)Ld;                     // f32 log(kappa_new)
        const float  w   = sqrtf(fmaf(x, x, 3969.0f));
        const float  dwx = 3969.0f / (w + x);             // w - x, stable
        const float  pp  = pser_f(63.0f / w);
        const float  lnS = pp - 0.5f * pp * pp;           // log1p(p), p small
        const double lnu_d = (double)dwx
                     - 63.0 * log1p((double)((63.0f + dwx) / x))
                     - 0.5 * (Ld + (double)log1pf(dwx / x))   // 0.5*log(w)
                     - 0.91893853320467274                    // 0.5*log(2*pi)
                     + (double)lnS
                     + (double)miller_corr(x);
        const float lnu = (float)lnu_d;

        // Reference's f32 association: ((lnu + x) - 63*L) - logc
        float r = __fsub_rn(__fsub_rn(__fadd_rn(lnu, x),
                                      __fmul_rn(63.0f, L)), lc);
        out[n * CC + c] = r;
    }
}

extern "C" void kernel_launch(void* const* d_in, const int* in_sizes, int n_in,
                              void* d_out, int out_size) {
    const float* feat  = (const float*)d_in[0];
    // d_in[1]: labels (int64) — unused by the deterministic forward math.
    const float* Ave   = (const float*)d_in[2];
    const float* kappa = (const float*)d_in[3];
    const float* logc  = (const float*)d_in[4];
    float* out = (float*)d_out;

    setup_kernel<<<CPAD / 8, 256>>>(Ave, kappa);
    proco_kernel<<<dim3((CC + TC - 1) / TC, NB / TN), 256>>>(feat, logc, out);
}

// round 8
// speedup vs baseline: 8.9943x; 8.9943x over previous
#include <cuda_runtime.h>
#include <math.h>

// ProCoUNLoss — f64-free hot path. Per-element f32 ops mirror the reference;
// reductions are exact; f64 log/log1p replaced by double-single (float-float)
// equivalents with abs error ~1e-9 (below the f32-rounding noise floor).

namespace {
constexpr int NB   = 256;
constexpr int DD   = 128;
constexpr int CC   = 1000;
constexpr int CPAD = 1024;
constexpr int TN   = 16;   // n tile
constexpr int TC   = 32;   // c tile
}

__device__ float g_proto[CPAD * DD];  // fl(kappa * Ave_norm), zero padded

// ---------- double-single log machinery (f32 pipe only) ----------
// Core: given m (DS: mh+ml) in [0.7071, 1.4143) and exponent e, return
// DS(hi,lo) of e*ln2 + log(m); abs err ~1e-9.
__device__ __forceinline__ float2 ds_log_core(float mh, float ml, float ef) {
    float ah = __fadd_rn(mh, -1.0f);               // exact (Sterbenz)
    float bh = __fadd_rn(mh, 1.0f);
    float tb = __fsub_rn(bh, 1.0f);                // TwoSum residual for m+1
    float bl = __fadd_rn(__fsub_rn(1.0f, __fsub_rn(bh, tb)), __fsub_rn(mh, tb));
    bl = __fadd_rn(bl, ml);
    float uh = __fdiv_rn(ah, bh);                  // u = (m-1)/(m+1), DS
    float rr = __fmaf_rn(-uh, bh, ah);
    rr = __fadd_rn(rr, __fsub_rn(ml, __fmul_rn(uh, bl)));
    float ul = __fdiv_rn(rr, bh);
    float u2 = __fmul_rn(uh, uh);                  // atanh series to u^9
    float p  = u2 * __fmaf_rn(u2, __fmaf_rn(u2, __fmaf_rn(u2, 0.11111111f,
                    0.14285715f), 0.2f), 0.33333334f);
    float lnmh = __fmul_rn(2.0f, uh);              // exact
    float lnml = __fmaf_rn(lnmh, p, __fmul_rn(2.0f, ul));
    const float LN2H = 0.6931471824645996f;
    const float LN2L = -1.9046542e-9f;
    float eh = __fmul_rn(ef, LN2H);
    float el = __fmaf_rn(ef, LN2H, -eh);
    el = __fmaf_rn(ef, LN2L, el);
    float sh = __fadd_rn(eh, lnmh);                // TwoSum(eh, lnmh)
    float ts = __fsub_rn(sh, eh);
    float sl = __fadd_rn(__fsub_rn(eh, __fsub_rn(sh, ts)), __fsub_rn(lnmh, ts));
    return make_float2(sh, __fadd_rn(sl, __fadd_rn(el, lnml)));
}

__device__ __forceinline__ float2 ds_log(float x) {   // x in [64, 4096]
    int ix = __float_as_int(x);
    int e  = ((ix >> 23) & 255) - 127;
    float m = __int_as_float((ix & 0x007fffff) | 0x3f800000);
    if (m > 1.4142135f) { m *= 0.5f; e += 1; }
    return ds_log_core(m, 0.0f, (float)e);
}

__device__ __forceinline__ float2 ds_log1p(float v) { // v in (0, 0.9]
    float sh = __fadd_rn(1.0f, v);                    // Fast2Sum (1 >= v)
    float sl = __fadd_rn(__fsub_rn(1.0f, sh), v);     // exact residual
    float ef = 0.0f;
    if (sh > 1.4142135f) { sh *= 0.5f; sl *= 0.5f; ef = 1.0f; }
    return ds_log_core(sh, sl, ef);
}

// log1p for z in [0, 0.19]: alternating series to z^9 (abs err < 5e-8)
__device__ __forceinline__ float log1p_small(float z) {
    float r = __fmaf_rn(z, 0.11111111f, -0.125f);
    r = __fmaf_rn(z, r, 0.14285715f);
    r = __fmaf_rn(z, r, -0.16666667f);
    r = __fmaf_rn(z, r, 0.2f);
    r = __fmaf_rn(z, r, -0.25f);
    r = __fmaf_rn(z, r, 0.33333334f);
    r = __fmaf_rn(z, r, -0.5f);
    r = __fmaf_rn(z, r, 1.0f);
    return __fmul_rn(z, r);
}

// p(t) = u1(t)/63 + u2(t)/63^2 + u3(t)/63^3  (Debye u-polynomials)
__device__ __forceinline__ float pser_f(float t) {
    float t2 = t * t;
    float a = t * (3.0f - 5.0f * t2) * (1.0f / 1512.0f);
    float b = t2 * (81.0f + t2 * (-462.0f + 385.0f * t2)) * 2.1870954e-7f;
    float c = t2 * t * (30375.0f + t2 * (-369603.0f + t2 * (765765.0f - 425425.0f * t2)))
              * 9.643249e-12f;
    return a + b + c;
}

// Miller-recurrence contamination of the reference (start M=126):
// log1p(-rho63) - log1p(rho0). w63/dw63/L63 are reused from the caller.
__device__ __forceinline__ float miller_corr(float x, float w63, float dw63,
                                             float L63) {
    float w127  = __fsqrt_rn(__fmaf_rn(x, x, 16129.0f));
    float dw127 = __fdividef(16129.0f, __fadd_rn(w127, x));
    float L127  = log1pf(__fdividef(__fadd_rn(127.0f, dw127), x));
    float g63 = __fmaf_rn(-254.0f, L127, __fmaf_rn(126.0f, L63,
                  2.0f * __fdividef(12160.0f, __fadd_rn(w127, w63))));
    float g0  = __fmaf_rn(-254.0f, L127, __fadd_rn(dw127, dw127));
    float r63 = __expf(g63);   // underflow to 0 at small x: correct
    float r0  = __expf(g0);
    return -(r63 + r0) - 0.5f * (r63 * r63 - r0 * r0);
}

// Full per-element epilogue: exact-sum -> x -> lnu -> reference association.
__device__ __forceinline__ float epilogue(float s, float kc, float lc) {
    // x = f32(sqrt(s+kc)) via Newton-refined DS sqrt (matches f64 path)
    float r0  = __fsqrt_rn(s);
    float e1  = __fmaf_rn(r0, r0, -s);                 // r0^2 - s (near-exact)
    float num = __fsub_rn(e1, kc);                     // r0^2 - (s+kc)
    float x   = __fsub_rn(r0, __fdiv_rn(num, __fadd_rn(r0, r0)));

    float w   = __fsqrt_rn(__fmaf_rn(x, x, 3969.0f));
    float dwx = __fdiv_rn(3969.0f, __fadd_rn(w, x));   // w - x, stable
    float v   = __fdiv_rn(__fadd_rn(63.0f, dwx), x);

    float2 lp = ds_log1p(v);                           // log1p(v), DS
    float t63h = __fmul_rn(63.0f, lp.x);
    float t63l = __fmaf_rn(63.0f, lp.x, -t63h);
    t63l = __fmaf_rn(63.0f, lp.y, t63l);

    float2 Lds = ds_log(x);
    float L    = __fadd_rn(Lds.x, Lds.y);              // f32 log(kappa_new)

    float L63  = log1pf(v);                            // for miller_corr (as R4)
    float hlw  = __fmul_rn(0.5f,
                   __fadd_rn(L, log1p_small(__fdiv_rn(dwx, x))));  // 0.5*log(w)
    float pp   = pser_f(__fdividef(63.0f, w));
    float lnS  = __fmaf_rn(-0.5f * pp, pp, pp);        // log1p(pp)
    float corr = miller_corr(x, w, dwx, L63);

    // lnu = dwx - 63*lp - 0.5*log(w) - 0.5*log(2pi) + lnS + corr  (DS accum)
    float Ah = __fadd_rn(dwx, -t63h);                  // TwoSum(dwx, -t63h)
    float t1 = __fsub_rn(Ah, dwx);
    float Al = __fadd_rn(__fsub_rn(dwx, __fsub_rn(Ah, t1)),
                         __fsub_rn(-t63h, t1));
    float Bh = __fadd_rn(Ah, -hlw);                    // TwoSum(Ah, -hlw)
    float t2 = __fsub_rn(Bh, Ah);
    float Bl = __fadd_rn(__fsub_rn(Ah, __fsub_rn(Bh, t2)),
                         __fsub_rn(-hlw, t2));
    float small = __fadd_rn(Al, Bl);
    small = __fadd_rn(small, -t63l);
    small = __fadd_rn(small, -0.91893853f);
    small = __fadd_rn(small, lnS);
    small = __fadd_rn(small, corr);
    float lnu = __fadd_rn(Bh, small);

    // Reference's f32 association: ((lnu + x) - 63*L) - logc
    return __fsub_rn(__fsub_rn(__fadd_rn(lnu, x), __fmul_rn(63.0f, L)), lc);
}

// Warp per class: f64 tree-reduced (order-free) exact norm, then
// proto = fl(kappa * fl(Ave/nrm)).
__global__ void setup_kernel(const float* __restrict__ Ave,
                             const float* __restrict__ kappa) {
    const int w    = threadIdx.x >> 5;
    const int lane = threadIdx.x & 31;
    const int c    = blockIdx.x * 8 + w;
    if (c >= CPAD) return;

    if (c < CC) {
        float r0 = Ave[c * DD + lane];
        float r1 = Ave[c * DD + lane + 32];
        float r2 = Ave[c * DD + lane + 64];
        float r3 = Ave[c * DD + lane + 96];
        double s = (double)__fmul_rn(r0, r0);
        s += (double)__fmul_rn(r1, r1);
        s += (double)__fmul_rn(r2, r2);
        s += (double)__fmul_rn(r3, r3);
        #pragma unroll
        for (int off = 16; off; off >>= 1)
            s += __shfl_xor_sync(0xffffffffu, s, off);
        float nrm = fmaxf((float)sqrt(s), 1e-12f);
        float kap = kappa[c];
        g_proto[c * DD + lane]      = __fmul_rn(kap, __fdiv_rn(r0, nrm));
        g_proto[c * DD + lane + 32] = __fmul_rn(kap, __fdiv_rn(r1, nrm));
        g_proto[c * DD + lane + 64] = __fmul_rn(kap, __fdiv_rn(r2, nrm));
        g_proto[c * DD + lane + 96] = __fmul_rn(kap, __fdiv_rn(r3, nrm));
    } else {
        #pragma unroll
        for (int j = 0; j < 4; ++j)
            g_proto[c * DD + lane + 32 * j] = 0.0f;
    }
}

// 16n x 32c tile, 256 threads, 2 outputs/thread. Exact sum of fl32(p+f)^2
// via fmaf groups-of-8 + Kahan across 16 groups.
__global__ __launch_bounds__(256, 4)
void proco_kernel(const float* __restrict__ feat,
                  const float* __restrict__ logc,
                  float* __restrict__ out) {
    __shared__ float fs[TN][DD + 4];
    __shared__ float ps[TC][DD + 4];

    const int c0  = blockIdx.x * TC;
    const int n0  = blockIdx.y * TN;
    const int tid = threadIdx.x;

    for (int i = tid; i < TN * DD / 4; i += 256) {
        int r = i >> 5, q = i & 31;
        *reinterpret_cast<float4*>(&fs[r][4 * q]) =
            reinterpret_cast<const float4*>(feat)[(n0 + r) * (DD / 4) + q];
    }
    for (int i = tid; i < TC * DD / 4; i += 256) {
        int r = i >> 5, q = i & 31;
        *reinterpret_cast<float4*>(&ps[r][4 * q]) =
            reinterpret_cast<const float4*>(g_proto)[(c0 + r) * (DD / 4) + q];
    }
    __syncthreads();

    const int cl = tid & 31;   // class lane (coalesced stores)
    const int ng = tid >> 5;   // n group; thread owns n = ng, ng+8

    float s[2]  = {0.f, 0.f};
    float kc[2] = {0.f, 0.f};  // Kahan compensation

    #pragma unroll
    for (int grp = 0; grp < 16; ++grp) {
        const int d0 = grp * 8;
        float4 pa = *reinterpret_cast<const float4*>(&ps[cl][d0]);
        float4 pb = *reinterpret_cast<const float4*>(&ps[cl][d0 + 4]);
        #pragma unroll
        for (int j = 0; j < 2; ++j) {
            float4 fa = *reinterpret_cast<const float4*>(&fs[ng + 8 * j][d0]);
            float4 fb = *reinterpret_cast<const float4*>(&fs[ng + 8 * j][d0 + 4]);
            float t, g;
            t = __fadd_rn(pa.x, fa.x); g = __fmul_rn(t, t);
            t = __fadd_rn(pa.y, fa.y); g = __fmaf_rn(t, t, g);
            t = __fadd_rn(pa.z, fa.z); g = __fmaf_rn(t, t, g);
            t = __fadd_rn(pa.w, fa.w); g = __fmaf_rn(t, t, g);
            t = __fadd_rn(pb.x, fb.x); g = __fmaf_rn(t, t, g);
            t = __fadd_rn(pb.y, fb.y); g = __fmaf_rn(t, t, g);
            t = __fadd_rn(pb.z, fb.z); g = __fmaf_rn(t, t, g);
            t = __fadd_rn(pb.w, fb.w); g = __fmaf_rn(t, t, g);
            float y  = __fsub_rn(g, kc[j]);            // Kahan
            float sn = __fadd_rn(s[j], y);
            kc[j] = __fsub_rn(__fsub_rn(sn, s[j]), y);
            s[j]  = sn;
        }
    }

    const int c = c0 + cl;
    if (c >= CC) return;
    const float lc = logc[c];

    #pragma unroll
    for (int j = 0; j < 2; ++j) {
        const int n = n0 + ng + 8 * j;
        out[n * CC + c] = epilogue(s[j], kc[j], lc);
    }
}

extern "C" void kernel_launch(void* const* d_in, const int* in_sizes, int n_in,
                              void* d_out, int out_size) {
    const float* feat  = (const float*)d_in[0];
    // d_in[1]: labels (int64) — unused by the deterministic forward math.
    const float* Ave   = (const float*)d_in[2];
    const float* kappa = (const float*)d_in[3];
    const float* logc  = (const float*)d_in[4];
    float* out = (float*)d_out;

    setup_kernel<<<CPAD / 8, 256>>>(Ave, kappa);
    proco_kernel<<<dim3((CC + TC - 1) / TC, NB / TN), 256>>>(feat, logc, out);
}